// round 1
// baseline (speedup 1.0000x reference)
#include <cuda_runtime.h>
#include <math.h>

// Problem constants
#define B 4
#define S 2048
#define E 1024
#define D 512
#define M_TOT (B * S)          // 8192

// Scratch (device globals: no allocation allowed in kernel_launch)
__device__ float g_Q[B * S * D];   // 16 MB
__device__ float g_K[B * S * D];   // 16 MB
__device__ float g_V[B * S * D];   // 16 MB
__device__ float g_P[(size_t)B * S * S]; // 64 MB

// ---------------------------------------------------------------------------
// Kernel 1: QKV projection.  X[8192,1024] @ W[1024,512] + bias -> {Q,K,V}
// 128x128x8 tile, 256 threads, 8x8 microtile.
// grid = (D/128=4, M/128=64, 3)
// ---------------------------------------------------------------------------
__global__ __launch_bounds__(256) void qkv_kernel(
    const float* __restrict__ X,
    const float* __restrict__ wq, const float* __restrict__ bq,
    const float* __restrict__ wk, const float* __restrict__ bk,
    const float* __restrict__ wv, const float* __restrict__ bv)
{
    const float* W; const float* bias; float* out;
    const int z = blockIdx.z;
    if (z == 0)      { W = wq; bias = bq; out = g_Q; }
    else if (z == 1) { W = wk; bias = bk; out = g_K; }
    else             { W = wv; bias = bv; out = g_V; }

    const int m0 = blockIdx.y * 128;
    const int n0 = blockIdx.x * 128;
    const int tid = threadIdx.x;

    __shared__ float As[8][128];
    __shared__ float Bs[8][128];

    const int a_row = tid >> 1;          // 0..127
    const int a_col = (tid & 1) * 4;     // 0 or 4
    const int b_row = tid >> 5;          // 0..7
    const int b_col = (tid & 31) * 4;    // 0..124

    const int ty = tid >> 4;             // 0..15
    const int tx = tid & 15;             // 0..15

    float acc[8][8];
#pragma unroll
    for (int i = 0; i < 8; i++)
#pragma unroll
        for (int j = 0; j < 8; j++) acc[i][j] = 0.f;

    for (int k0 = 0; k0 < E; k0 += 8) {
        float4 av = *(const float4*)(X + (size_t)(m0 + a_row) * E + k0 + a_col);
        float4 bv4 = *(const float4*)(W + (size_t)(k0 + b_row) * D + n0 + b_col);
        As[a_col + 0][a_row] = av.x;
        As[a_col + 1][a_row] = av.y;
        As[a_col + 2][a_row] = av.z;
        As[a_col + 3][a_row] = av.w;
        *(float4*)(&Bs[b_row][b_col]) = bv4;
        __syncthreads();
#pragma unroll
        for (int kk = 0; kk < 8; kk++) {
            float a[8], bb[8];
#pragma unroll
            for (int i = 0; i < 8; i++) a[i] = As[kk][ty * 8 + i];
#pragma unroll
            for (int j = 0; j < 8; j++) bb[j] = Bs[kk][tx * 8 + j];
#pragma unroll
            for (int i = 0; i < 8; i++)
#pragma unroll
                for (int j = 0; j < 8; j++) acc[i][j] += a[i] * bb[j];
        }
        __syncthreads();
    }

#pragma unroll
    for (int i = 0; i < 8; i++) {
        const int m = m0 + ty * 8 + i;
#pragma unroll
        for (int j = 0; j < 8; j++) {
            const int n = n0 + tx * 8 + j;
            out[(size_t)m * D + n] = acc[i][j] + bias[n];
        }
    }
}

// ---------------------------------------------------------------------------
// Kernel 2: causal scores.  P[b,i,j] = (Q_i . K_j) / sqrt(D), j<=i else -1e30
// Only lower-triangular 128x128 tiles are computed.
// grid = (S/128=16, S/128=16, B)
// ---------------------------------------------------------------------------
__global__ __launch_bounds__(256) void scores_kernel()
{
    const int nt = blockIdx.x;
    const int mt = blockIdx.y;
    if (nt > mt) return;                 // strictly upper tiles untouched
    const int b = blockIdx.z;

    const float* Q = g_Q + (size_t)b * S * D;
    const float* K = g_K + (size_t)b * S * D;
    float* P = g_P + (size_t)b * S * S;

    const int m0 = mt * 128;
    const int n0 = nt * 128;
    const int tid = threadIdx.x;

    __shared__ float As[8][128];
    __shared__ float Bs[8][128];

    const int l_row = tid >> 1;
    const int l_col = (tid & 1) * 4;

    const int ty = tid >> 4;
    const int tx = tid & 15;

    float acc[8][8];
#pragma unroll
    for (int i = 0; i < 8; i++)
#pragma unroll
        for (int j = 0; j < 8; j++) acc[i][j] = 0.f;

    for (int k0 = 0; k0 < D; k0 += 8) {
        float4 av = *(const float4*)(Q + (size_t)(m0 + l_row) * D + k0 + l_col);
        float4 kv = *(const float4*)(K + (size_t)(n0 + l_row) * D + k0 + l_col);
        As[l_col + 0][l_row] = av.x;
        As[l_col + 1][l_row] = av.y;
        As[l_col + 2][l_row] = av.z;
        As[l_col + 3][l_row] = av.w;
        Bs[l_col + 0][l_row] = kv.x;
        Bs[l_col + 1][l_row] = kv.y;
        Bs[l_col + 2][l_row] = kv.z;
        Bs[l_col + 3][l_row] = kv.w;
        __syncthreads();
#pragma unroll
        for (int kk = 0; kk < 8; kk++) {
            float a[8], bb[8];
#pragma unroll
            for (int i = 0; i < 8; i++) a[i] = As[kk][ty * 8 + i];
#pragma unroll
            for (int j = 0; j < 8; j++) bb[j] = Bs[kk][tx * 8 + j];
#pragma unroll
            for (int i = 0; i < 8; i++)
#pragma unroll
                for (int j = 0; j < 8; j++) acc[i][j] += a[i] * bb[j];
        }
        __syncthreads();
    }

    const float inv_sqrt_d = rsqrtf((float)D);
#pragma unroll
    for (int i = 0; i < 8; i++) {
        const int gi = m0 + ty * 8 + i;
#pragma unroll
        for (int j = 0; j < 8; j++) {
            const int gj = n0 + tx * 8 + j;
            float v = (gj <= gi) ? acc[i][j] * inv_sqrt_d : -1e30f;
            P[(size_t)gi * S + gj] = v;
        }
    }
}

// ---------------------------------------------------------------------------
// Kernel 3: row softmax.  One block per row; zero-fills masked tail up to the
// 128-aligned row end so the PV GEMM reads only defined data.
// grid = (S, B), 256 threads
// ---------------------------------------------------------------------------
__global__ __launch_bounds__(256) void softmax_kernel()
{
    const int i = blockIdx.x;
    const int b = blockIdx.y;
    float* row = g_P + ((size_t)b * S + i) * S;
    const int tid = threadIdx.x;
    const int Jend = ((i >> 7) + 1) << 7;   // round_up(i+1, 128)

    __shared__ float red[256];

    float m = -INFINITY;
    for (int j = tid; j <= i; j += 256) m = fmaxf(m, row[j]);
    red[tid] = m;
    __syncthreads();
    for (int s = 128; s > 0; s >>= 1) {
        if (tid < s) red[tid] = fmaxf(red[tid], red[tid + s]);
        __syncthreads();
    }
    const float mx = red[0];
    __syncthreads();

    float sum = 0.f;
    for (int j = tid; j < Jend; j += 256) {
        if (j <= i) {
            float e = __expf(row[j] - mx);
            row[j] = e;
            sum += e;
        } else {
            row[j] = 0.f;
        }
    }
    red[tid] = sum;
    __syncthreads();
    for (int s = 128; s > 0; s >>= 1) {
        if (tid < s) red[tid] += red[tid + s];
        __syncthreads();
    }
    const float inv = 1.f / red[0];

    for (int j = tid; j <= i; j += 256) row[j] *= inv;
}

// ---------------------------------------------------------------------------
// Kernel 4: O = P @ V with causal k-loop truncation.
// grid = (D/128=4, S/128=16, B)
// ---------------------------------------------------------------------------
__global__ __launch_bounds__(256) void pv_kernel(float* __restrict__ out)
{
    const int nt = blockIdx.x;
    const int mt = blockIdx.y;
    const int b = blockIdx.z;

    const float* P = g_P + (size_t)b * S * S;
    const float* V = g_V + (size_t)b * S * D;
    float* O = out + (size_t)b * S * D;

    const int m0 = mt * 128;
    const int n0 = nt * 128;
    const int tid = threadIdx.x;
    const int kmax = (mt + 1) * 128;     // causal bound

    __shared__ float As[8][128];
    __shared__ float Bs[8][128];

    const int a_row = tid >> 1;
    const int a_col = (tid & 1) * 4;
    const int b_row = tid >> 5;
    const int b_col = (tid & 31) * 4;

    const int ty = tid >> 4;
    const int tx = tid & 15;

    float acc[8][8];
#pragma unroll
    for (int i = 0; i < 8; i++)
#pragma unroll
        for (int j = 0; j < 8; j++) acc[i][j] = 0.f;

    for (int k0 = 0; k0 < kmax; k0 += 8) {
        float4 av = *(const float4*)(P + (size_t)(m0 + a_row) * S + k0 + a_col);
        float4 bv4 = *(const float4*)(V + (size_t)(k0 + b_row) * D + n0 + b_col);
        As[a_col + 0][a_row] = av.x;
        As[a_col + 1][a_row] = av.y;
        As[a_col + 2][a_row] = av.z;
        As[a_col + 3][a_row] = av.w;
        *(float4*)(&Bs[b_row][b_col]) = bv4;
        __syncthreads();
#pragma unroll
        for (int kk = 0; kk < 8; kk++) {
            float a[8], bb[8];
#pragma unroll
            for (int i = 0; i < 8; i++) a[i] = As[kk][ty * 8 + i];
#pragma unroll
            for (int j = 0; j < 8; j++) bb[j] = Bs[kk][tx * 8 + j];
#pragma unroll
            for (int i = 0; i < 8; i++)
#pragma unroll
                for (int j = 0; j < 8; j++) acc[i][j] += a[i] * bb[j];
        }
        __syncthreads();
    }

#pragma unroll
    for (int i = 0; i < 8; i++) {
        const int m = m0 + ty * 8 + i;
#pragma unroll
        for (int j = 0; j < 8; j++) {
            const int n = n0 + tx * 8 + j;
            O[(size_t)m * D + n] = acc[i][j];
        }
    }
}

// ---------------------------------------------------------------------------
extern "C" void kernel_launch(void* const* d_in, const int* in_sizes, int n_in,
                              void* d_out, int out_size)
{
    const float* x  = (const float*)d_in[0];
    const float* wq = (const float*)d_in[1];
    const float* bq = (const float*)d_in[2];
    const float* wk = (const float*)d_in[3];
    const float* bk = (const float*)d_in[4];
    const float* wv = (const float*)d_in[5];
    const float* bv = (const float*)d_in[6];
    float* out = (float*)d_out;

    dim3 blk(256);

    // 1) QKV projections
    qkv_kernel<<<dim3(D / 128, M_TOT / 128, 3), blk>>>(x, wq, bq, wk, bk, wv, bv);

    // 2) causal scores
    scores_kernel<<<dim3(S / 128, S / 128, B), blk>>>();

    // 3) row softmax
    softmax_kernel<<<dim3(S, B), blk>>>();

    // 4) O = P @ V
    pv_kernel<<<dim3(D / 128, S / 128, B), blk>>>(out);
}

// round 2
// speedup vs baseline: 2.9266x; 2.9266x over previous
#include <cuda_runtime.h>
#include <math.h>
#include <stdint.h>

// Problem constants
#define B 4
#define S 2048
#define E 1024
#define D 512
#define M_TOT (B * S)          // 8192

// Scratch
__device__ float g_Q[B * S * D];
__device__ float g_K[B * S * D];
__device__ float g_V[B * S * D];
__device__ float g_P[(size_t)B * S * S];

// ---------------------------------------------------------------------------
// TF32 mma helpers
// ---------------------------------------------------------------------------
__device__ __forceinline__ uint32_t f2tf32(float x) {
    uint32_t r;
    asm("cvt.rna.tf32.f32 %0, %1;" : "=r"(r) : "f"(x));
    return r;
}

__device__ __forceinline__ void mma_tf32(float d[4], const uint32_t a[4], const uint32_t b[2]) {
    asm volatile(
        "mma.sync.aligned.m16n8k8.row.col.f32.tf32.tf32.f32 "
        "{%0,%1,%2,%3}, {%4,%5,%6,%7}, {%8,%9}, {%0,%1,%2,%3};\n"
        : "+f"(d[0]), "+f"(d[1]), "+f"(d[2]), "+f"(d[3])
        : "r"(a[0]), "r"(a[1]), "r"(a[2]), "r"(a[3]), "r"(b[0]), "r"(b[1]));
}

// Shared-tile paddings (bank-conflict free fragment loads)
#define APAD 36    // 128 x 36 floats  (A tiles, and K tile in scores)
#define BPAD 136   // 32 x 136 floats  (row-major k x n B tiles)

// ---------------------------------------------------------------------------
// Kernel 1: QKV projection with tensor cores.
// grid = (D/128=4, M/128=64, 3), 256 threads
// ---------------------------------------------------------------------------
__global__ __launch_bounds__(256, 2) void qkv_tc(
    const float* __restrict__ X,
    const float* __restrict__ wq, const float* __restrict__ bq,
    const float* __restrict__ wk, const float* __restrict__ bk,
    const float* __restrict__ wv, const float* __restrict__ bv)
{
    const float* W; const float* bias; float* out;
    const int z = blockIdx.z;
    if (z == 0)      { W = wq; bias = bq; out = g_Q; }
    else if (z == 1) { W = wk; bias = bk; out = g_K; }
    else             { W = wv; bias = bv; out = g_V; }

    __shared__ float As[128][APAD];
    __shared__ float Bs[32][BPAD];

    const int m0 = blockIdx.y * 128;
    const int n0 = blockIdx.x * 128;
    const int tid = threadIdx.x;
    const int warp = tid >> 5;
    const int lane = tid & 31;
    const int g = lane >> 2;
    const int tg = lane & 3;
    const int wm = (warp >> 2) * 64;
    const int wn = (warp & 3) * 32;

    const int ar = tid >> 3;            // 0..31
    const int ac = (tid & 7) * 4;       // 0..28
    const int br = tid >> 5;            // 0..7
    const int bc = (tid & 31) * 4;      // 0..124

    float acc[4][4][4];
#pragma unroll
    for (int mi = 0; mi < 4; mi++)
#pragma unroll
        for (int ni = 0; ni < 4; ni++)
#pragma unroll
            for (int r = 0; r < 4; r++) acc[mi][ni][r] = 0.f;

    for (int k0 = 0; k0 < E; k0 += 32) {
#pragma unroll
        for (int it = 0; it < 4; it++) {
            int row = ar + it * 32;
            *(float4*)&As[row][ac] = *(const float4*)(X + (size_t)(m0 + row) * E + k0 + ac);
        }
#pragma unroll
        for (int it = 0; it < 4; it++) {
            int row = br + it * 8;
            *(float4*)&Bs[row][bc] = *(const float4*)(W + (size_t)(k0 + row) * D + n0 + bc);
        }
        __syncthreads();

#pragma unroll
        for (int ks = 0; ks < 32; ks += 8) {
            uint32_t af[4][4];
#pragma unroll
            for (int mi = 0; mi < 4; mi++) {
                int r = wm + mi * 16 + g;
                af[mi][0] = f2tf32(As[r][ks + tg]);
                af[mi][1] = f2tf32(As[r + 8][ks + tg]);
                af[mi][2] = f2tf32(As[r][ks + tg + 4]);
                af[mi][3] = f2tf32(As[r + 8][ks + tg + 4]);
            }
            uint32_t bf[4][2];
#pragma unroll
            for (int ni = 0; ni < 4; ni++) {
                int c = wn + ni * 8 + g;
                bf[ni][0] = f2tf32(Bs[ks + tg][c]);
                bf[ni][1] = f2tf32(Bs[ks + tg + 4][c]);
            }
#pragma unroll
            for (int mi = 0; mi < 4; mi++)
#pragma unroll
                for (int ni = 0; ni < 4; ni++)
                    mma_tf32(acc[mi][ni], af[mi], bf[ni]);
        }
        __syncthreads();
    }

#pragma unroll
    for (int mi = 0; mi < 4; mi++) {
        int row0 = m0 + wm + mi * 16 + g;
#pragma unroll
        for (int ni = 0; ni < 4; ni++) {
            int col = n0 + wn + ni * 8 + 2 * tg;
            float b0 = bias[col], b1 = bias[col + 1];
            float2 v0 = {acc[mi][ni][0] + b0, acc[mi][ni][1] + b1};
            float2 v1 = {acc[mi][ni][2] + b0, acc[mi][ni][3] + b1};
            *(float2*)(out + (size_t)row0 * D + col) = v0;
            *(float2*)(out + (size_t)(row0 + 8) * D + col) = v1;
        }
    }
}

// ---------------------------------------------------------------------------
// Kernel 2: causal scores with tensor cores. P = (Q . K^T)/sqrt(D), masked.
// grid = (16, 16, B); upper tiles early-exit.
// ---------------------------------------------------------------------------
__global__ __launch_bounds__(256, 2) void scores_tc()
{
    const int nt = blockIdx.x;
    const int mt = blockIdx.y;
    if (nt > mt) return;
    const int b = blockIdx.z;

    const float* Q = g_Q + (size_t)b * S * D;
    const float* K = g_K + (size_t)b * S * D;
    float* P = g_P + (size_t)b * S * S;

    __shared__ float As[128][APAD];
    __shared__ float Ks[128][APAD];

    const int m0 = mt * 128;
    const int n0 = nt * 128;
    const int tid = threadIdx.x;
    const int warp = tid >> 5;
    const int lane = tid & 31;
    const int g = lane >> 2;
    const int tg = lane & 3;
    const int wm = (warp >> 2) * 64;
    const int wn = (warp & 3) * 32;

    const int ar = tid >> 3;
    const int ac = (tid & 7) * 4;

    float acc[4][4][4];
#pragma unroll
    for (int mi = 0; mi < 4; mi++)
#pragma unroll
        for (int ni = 0; ni < 4; ni++)
#pragma unroll
            for (int r = 0; r < 4; r++) acc[mi][ni][r] = 0.f;

    for (int k0 = 0; k0 < D; k0 += 32) {
#pragma unroll
        for (int it = 0; it < 4; it++) {
            int row = ar + it * 32;
            *(float4*)&As[row][ac] = *(const float4*)(Q + (size_t)(m0 + row) * D + k0 + ac);
            *(float4*)&Ks[row][ac] = *(const float4*)(K + (size_t)(n0 + row) * D + k0 + ac);
        }
        __syncthreads();

#pragma unroll
        for (int ks = 0; ks < 32; ks += 8) {
            uint32_t af[4][4];
#pragma unroll
            for (int mi = 0; mi < 4; mi++) {
                int r = wm + mi * 16 + g;
                af[mi][0] = f2tf32(As[r][ks + tg]);
                af[mi][1] = f2tf32(As[r + 8][ks + tg]);
                af[mi][2] = f2tf32(As[r][ks + tg + 4]);
                af[mi][3] = f2tf32(As[r + 8][ks + tg + 4]);
            }
            uint32_t bf[4][2];
#pragma unroll
            for (int ni = 0; ni < 4; ni++) {
                int c = wn + ni * 8 + g;
                bf[ni][0] = f2tf32(Ks[c][ks + tg]);
                bf[ni][1] = f2tf32(Ks[c][ks + tg + 4]);
            }
#pragma unroll
            for (int mi = 0; mi < 4; mi++)
#pragma unroll
                for (int ni = 0; ni < 4; ni++)
                    mma_tf32(acc[mi][ni], af[mi], bf[ni]);
        }
        __syncthreads();
    }

    const float scale = rsqrtf((float)D);
#pragma unroll
    for (int mi = 0; mi < 4; mi++) {
        int gi0 = m0 + wm + mi * 16 + g;
#pragma unroll
        for (int ni = 0; ni < 4; ni++) {
            int gj = n0 + wn + ni * 8 + 2 * tg;
            float2 v0, v1;
            v0.x = (gj     <= gi0) ? acc[mi][ni][0] * scale : -1e30f;
            v0.y = (gj + 1 <= gi0) ? acc[mi][ni][1] * scale : -1e30f;
            v1.x = (gj     <= gi0 + 8) ? acc[mi][ni][2] * scale : -1e30f;
            v1.y = (gj + 1 <= gi0 + 8) ? acc[mi][ni][3] * scale : -1e30f;
            *(float2*)(P + (size_t)gi0 * S + gj) = v0;
            *(float2*)(P + (size_t)(gi0 + 8) * S + gj) = v1;
        }
    }
}

// ---------------------------------------------------------------------------
// Kernel 3: row softmax (unchanged). grid = (S, B), 256 threads
// ---------------------------------------------------------------------------
__global__ __launch_bounds__(256) void softmax_kernel()
{
    const int i = blockIdx.x;
    const int b = blockIdx.y;
    float* row = g_P + ((size_t)b * S + i) * S;
    const int tid = threadIdx.x;
    const int Jend = ((i >> 7) + 1) << 7;

    __shared__ float red[256];

    float m = -INFINITY;
    for (int j = tid; j <= i; j += 256) m = fmaxf(m, row[j]);
    red[tid] = m;
    __syncthreads();
    for (int s = 128; s > 0; s >>= 1) {
        if (tid < s) red[tid] = fmaxf(red[tid], red[tid + s]);
        __syncthreads();
    }
    const float mx = red[0];
    __syncthreads();

    float sum = 0.f;
    for (int j = tid; j < Jend; j += 256) {
        if (j <= i) {
            float e = __expf(row[j] - mx);
            row[j] = e;
            sum += e;
        } else {
            row[j] = 0.f;
        }
    }
    red[tid] = sum;
    __syncthreads();
    for (int s = 128; s > 0; s >>= 1) {
        if (tid < s) red[tid] += red[tid + s];
        __syncthreads();
    }
    const float inv = 1.f / red[0];

    for (int j = tid; j <= i; j += 256) row[j] *= inv;
}

// ---------------------------------------------------------------------------
// Kernel 4: O = P @ V with tensor cores, causal k truncation.
// grid = (D/128=4, S/128=16, B)
// ---------------------------------------------------------------------------
__global__ __launch_bounds__(256, 2) void pv_tc(float* __restrict__ outp)
{
    const int nt = blockIdx.x;
    const int mt = blockIdx.y;
    const int b = blockIdx.z;

    const float* P = g_P + (size_t)b * S * S;
    const float* V = g_V + (size_t)b * S * D;
    float* O = outp + (size_t)b * S * D;

    __shared__ float As[128][APAD];
    __shared__ float Bs[32][BPAD];

    const int m0 = mt * 128;
    const int n0 = nt * 128;
    const int tid = threadIdx.x;
    const int warp = tid >> 5;
    const int lane = tid & 31;
    const int g = lane >> 2;
    const int tg = lane & 3;
    const int wm = (warp >> 2) * 64;
    const int wn = (warp & 3) * 32;
    const int kmax = (mt + 1) * 128;

    const int ar = tid >> 3;
    const int ac = (tid & 7) * 4;
    const int br = tid >> 5;
    const int bc = (tid & 31) * 4;

    float acc[4][4][4];
#pragma unroll
    for (int mi = 0; mi < 4; mi++)
#pragma unroll
        for (int ni = 0; ni < 4; ni++)
#pragma unroll
            for (int r = 0; r < 4; r++) acc[mi][ni][r] = 0.f;

    for (int k0 = 0; k0 < kmax; k0 += 32) {
#pragma unroll
        for (int it = 0; it < 4; it++) {
            int row = ar + it * 32;
            *(float4*)&As[row][ac] = *(const float4*)(P + (size_t)(m0 + row) * S + k0 + ac);
        }
#pragma unroll
        for (int it = 0; it < 4; it++) {
            int row = br + it * 8;
            *(float4*)&Bs[row][bc] = *(const float4*)(V + (size_t)(k0 + row) * D + n0 + bc);
        }
        __syncthreads();

#pragma unroll
        for (int ks = 0; ks < 32; ks += 8) {
            uint32_t af[4][4];
#pragma unroll
            for (int mi = 0; mi < 4; mi++) {
                int r = wm + mi * 16 + g;
                af[mi][0] = f2tf32(As[r][ks + tg]);
                af[mi][1] = f2tf32(As[r + 8][ks + tg]);
                af[mi][2] = f2tf32(As[r][ks + tg + 4]);
                af[mi][3] = f2tf32(As[r + 8][ks + tg + 4]);
            }
            uint32_t bf[4][2];
#pragma unroll
            for (int ni = 0; ni < 4; ni++) {
                int c = wn + ni * 8 + g;
                bf[ni][0] = f2tf32(Bs[ks + tg][c]);
                bf[ni][1] = f2tf32(Bs[ks + tg + 4][c]);
            }
#pragma unroll
            for (int mi = 0; mi < 4; mi++)
#pragma unroll
                for (int ni = 0; ni < 4; ni++)
                    mma_tf32(acc[mi][ni], af[mi], bf[ni]);
        }
        __syncthreads();
    }

#pragma unroll
    for (int mi = 0; mi < 4; mi++) {
        int row0 = m0 + wm + mi * 16 + g;
#pragma unroll
        for (int ni = 0; ni < 4; ni++) {
            int col = n0 + wn + ni * 8 + 2 * tg;
            float2 v0 = {acc[mi][ni][0], acc[mi][ni][1]};
            float2 v1 = {acc[mi][ni][2], acc[mi][ni][3]};
            *(float2*)(O + (size_t)row0 * D + col) = v0;
            *(float2*)(O + (size_t)(row0 + 8) * D + col) = v1;
        }
    }
}

// ---------------------------------------------------------------------------
extern "C" void kernel_launch(void* const* d_in, const int* in_sizes, int n_in,
                              void* d_out, int out_size)
{
    const float* x  = (const float*)d_in[0];
    const float* wq = (const float*)d_in[1];
    const float* bq = (const float*)d_in[2];
    const float* wk = (const float*)d_in[3];
    const float* bk = (const float*)d_in[4];
    const float* wv = (const float*)d_in[5];
    const float* bv = (const float*)d_in[6];
    float* out = (float*)d_out;

    dim3 blk(256);

    qkv_tc<<<dim3(D / 128, M_TOT / 128, 3), blk>>>(x, wq, bq, wk, bk, wv, bv);
    scores_tc<<<dim3(S / 128, S / 128, B), blk>>>();
    softmax_kernel<<<dim3(S, B), blk>>>();
    pv_tc<<<dim3(D / 128, S / 128, B), blk>>>(out);
}

// round 3
// speedup vs baseline: 3.8810x; 1.3261x over previous
#include <cuda_runtime.h>
#include <math.h>
#include <stdint.h>

#define B 4
#define S 2048
#define E 1024
#define D 512
#define M_TOT (B * S)

// Scratch
__device__ float g_Q[B * S * D];
__device__ float g_K[B * S * D];
__device__ float g_V[B * S * D];
__device__ float g_P[(size_t)B * S * S];
__device__ float g_sum[B * S];

#define APAD 36            // padded A rows (floats): conflict-free ldmatrix
#define BPAD 136           // padded B rows (floats): conflict-free scalar LDS
#define A_STAGE (128 * APAD)   // 4608 floats
#define B_STAGE (32 * BPAD)    // 4352 floats

__device__ __forceinline__ uint32_t f2tf32(float x) {
    uint32_t r;
    asm("cvt.rna.tf32.f32 %0, %1;" : "=r"(r) : "f"(x));
    return r;
}
__device__ __forceinline__ void mma_tf32(float d[4], const uint32_t a[4], const uint32_t b[2]) {
    asm volatile(
        "mma.sync.aligned.m16n8k8.row.col.f32.tf32.tf32.f32 "
        "{%0,%1,%2,%3}, {%4,%5,%6,%7}, {%8,%9}, {%0,%1,%2,%3};\n"
        : "+f"(d[0]), "+f"(d[1]), "+f"(d[2]), "+f"(d[3])
        : "r"(a[0]), "r"(a[1]), "r"(a[2]), "r"(a[3]), "r"(b[0]), "r"(b[1]));
}
__device__ __forceinline__ void ldsm4(uint32_t& r0, uint32_t& r1, uint32_t& r2, uint32_t& r3,
                                      uint32_t addr) {
    asm volatile("ldmatrix.sync.aligned.m8n8.x4.shared.b16 {%0,%1,%2,%3}, [%4];"
                 : "=r"(r0), "=r"(r1), "=r"(r2), "=r"(r3) : "r"(addr));
}
__device__ __forceinline__ void cpa16(uint32_t dst, const float* src) {
    asm volatile("cp.async.cg.shared.global [%0], [%1], 16;" :: "r"(dst), "l"(src));
}
__device__ __forceinline__ void cpa_commit() { asm volatile("cp.async.commit_group;"); }
__device__ __forceinline__ void cpa_wait1() { asm volatile("cp.async.wait_group 1;"); }
__device__ __forceinline__ void cpa_wait0() { asm volatile("cp.async.wait_group 0;"); }

// ---------------------------------------------------------------------------
// Kernel 1: QKV projection. grid=(4, 64, 3), 256 thr, 2-stage cp.async
// ---------------------------------------------------------------------------
__global__ __launch_bounds__(256, 2) void qkv_tc(
    const float* __restrict__ X,
    const float* __restrict__ wq, const float* __restrict__ bq,
    const float* __restrict__ wk, const float* __restrict__ bk,
    const float* __restrict__ wv, const float* __restrict__ bv)
{
    extern __shared__ float smem[];
    float* AsF = smem;                       // [2][128][APAD]
    float* BsF = smem + 2 * A_STAGE;         // [2][32][BPAD]
    const uint32_t as_u = (uint32_t)__cvta_generic_to_shared(AsF);

    const float* W; const float* bias; float* out;
    const int z = blockIdx.z;
    if (z == 0)      { W = wq; bias = bq; out = g_Q; }
    else if (z == 1) { W = wk; bias = bk; out = g_K; }
    else             { W = wv; bias = bv; out = g_V; }

    const int m0 = blockIdx.y * 128;
    const int n0 = blockIdx.x * 128;
    const int tid = threadIdx.x;
    const int warp = tid >> 5, lane = tid & 31;
    const int g = lane >> 2, tg = lane & 3;
    const int sub = lane >> 3, li = lane & 7;
    const int wm = (warp >> 2) * 64, wn = (warp & 3) * 32;

    const int ar = tid >> 3, ac = (tid & 7) * 4;
    const int br = tid >> 5, bc = (tid & 31) * 4;

    // ldmatrix A offsets (floats) per mi
    int a_off[4];
#pragma unroll
    for (int mi = 0; mi < 4; mi++)
        a_off[mi] = (wm + mi * 16 + (sub & 1) * 8 + li) * APAD + (sub >> 1) * 4;

    float acc[4][4][4];
#pragma unroll
    for (int mi = 0; mi < 4; mi++)
#pragma unroll
        for (int ni = 0; ni < 4; ni++)
#pragma unroll
            for (int r = 0; r < 4; r++) acc[mi][ni][r] = 0.f;

    // stage loader
    auto load_stage = [&](int st, int k0) {
#pragma unroll
        for (int it = 0; it < 4; it++) {
            int row = ar + it * 32;
            cpa16(as_u + (uint32_t)(st * A_STAGE + row * APAD + ac) * 4,
                  X + (size_t)(m0 + row) * E + k0 + ac);
        }
        uint32_t bs_u = as_u + 2u * A_STAGE * 4;
#pragma unroll
        for (int it = 0; it < 4; it++) {
            int row = br + it * 8;
            cpa16(bs_u + (uint32_t)(st * B_STAGE + row * BPAD + bc) * 4,
                  W + (size_t)(k0 + row) * D + n0 + bc);
        }
        cpa_commit();
    };

    load_stage(0, 0);
    int s = 0;
    for (int k0 = 0; k0 < E; k0 += 32, s ^= 1) {
        const bool has_next = (k0 + 32 < E);
        if (has_next) { load_stage(s ^ 1, k0 + 32); cpa_wait1(); }
        else          { cpa_wait0(); }
        __syncthreads();

#pragma unroll
        for (int ks = 0; ks < 32; ks += 8) {
            uint32_t af[4][4];
#pragma unroll
            for (int mi = 0; mi < 4; mi++) {
                ldsm4(af[mi][0], af[mi][1], af[mi][2], af[mi][3],
                      as_u + (uint32_t)(s * A_STAGE + a_off[mi] + ks) * 4);
#pragma unroll
                for (int r = 0; r < 4; r++)
                    af[mi][r] = f2tf32(__uint_as_float(af[mi][r]));
            }
            uint32_t bf[4][2];
#pragma unroll
            for (int ni = 0; ni < 4; ni++) {
                const float* bp = BsF + s * B_STAGE + (ks + tg) * BPAD + wn + ni * 8 + g;
                bf[ni][0] = f2tf32(bp[0]);
                bf[ni][1] = f2tf32(bp[4 * BPAD]);
            }
#pragma unroll
            for (int mi = 0; mi < 4; mi++)
#pragma unroll
                for (int ni = 0; ni < 4; ni++)
                    mma_tf32(acc[mi][ni], af[mi], bf[ni]);
        }
        __syncthreads();
    }

    // epilogue: add bias, round to tf32 so downstream GEMMs need no cvt
#pragma unroll
    for (int mi = 0; mi < 4; mi++) {
        int row0 = m0 + wm + mi * 16 + g;
#pragma unroll
        for (int ni = 0; ni < 4; ni++) {
            int col = n0 + wn + ni * 8 + 2 * tg;
            float b0 = bias[col], b1 = bias[col + 1];
            float2 v0, v1;
            v0.x = __uint_as_float(f2tf32(acc[mi][ni][0] + b0));
            v0.y = __uint_as_float(f2tf32(acc[mi][ni][1] + b1));
            v1.x = __uint_as_float(f2tf32(acc[mi][ni][2] + b0));
            v1.y = __uint_as_float(f2tf32(acc[mi][ni][3] + b1));
            *(float2*)(out + (size_t)row0 * D + col) = v0;
            *(float2*)(out + (size_t)(row0 + 8) * D + col) = v1;
        }
    }
}

// ---------------------------------------------------------------------------
// Kernel 2: causal scores. grid=(16,16,B). ldmatrix both operands, no cvt.
// No masking: softmax only reads j<=i and zero-fills the tail.
// ---------------------------------------------------------------------------
__global__ __launch_bounds__(256, 2) void scores_tc()
{
    const int nt = blockIdx.x;
    const int mt = blockIdx.y;
    if (nt > mt) return;
    const int b = blockIdx.z;

    extern __shared__ float smem[];
    const uint32_t as_u = (uint32_t)__cvta_generic_to_shared(smem);
    const uint32_t ks_u = as_u + 2u * A_STAGE * 4;

    const float* Q = g_Q + (size_t)b * S * D;
    const float* K = g_K + (size_t)b * S * D;
    float* P = g_P + (size_t)b * S * S;

    const int m0 = mt * 128;
    const int n0 = nt * 128;
    const int tid = threadIdx.x;
    const int warp = tid >> 5, lane = tid & 31;
    const int g = lane >> 2, tg = lane & 3;
    const int sub = lane >> 3, li = lane & 7;
    const int wm = (warp >> 2) * 64, wn = (warp & 3) * 32;
    const int ar = tid >> 3, ac = (tid & 7) * 4;

    int a_off[4], b_off[2];
#pragma unroll
    for (int mi = 0; mi < 4; mi++)
        a_off[mi] = (wm + mi * 16 + (sub & 1) * 8 + li) * APAD + (sub >> 1) * 4;
#pragma unroll
    for (int np = 0; np < 2; np++)
        b_off[np] = (wn + np * 16 + (sub >> 1) * 8 + li) * APAD + (sub & 1) * 4;

    float acc[4][4][4];
#pragma unroll
    for (int mi = 0; mi < 4; mi++)
#pragma unroll
        for (int ni = 0; ni < 4; ni++)
#pragma unroll
            for (int r = 0; r < 4; r++) acc[mi][ni][r] = 0.f;

    auto load_stage = [&](int st, int k0) {
#pragma unroll
        for (int it = 0; it < 4; it++) {
            int row = ar + it * 32;
            cpa16(as_u + (uint32_t)(st * A_STAGE + row * APAD + ac) * 4,
                  Q + (size_t)(m0 + row) * D + k0 + ac);
            cpa16(ks_u + (uint32_t)(st * A_STAGE + row * APAD + ac) * 4,
                  K + (size_t)(n0 + row) * D + k0 + ac);
        }
        cpa_commit();
    };

    load_stage(0, 0);
    int s = 0;
    for (int k0 = 0; k0 < D; k0 += 32, s ^= 1) {
        const bool has_next = (k0 + 32 < D);
        if (has_next) { load_stage(s ^ 1, k0 + 32); cpa_wait1(); }
        else          { cpa_wait0(); }
        __syncthreads();

#pragma unroll
        for (int ks = 0; ks < 32; ks += 8) {
            uint32_t af[4][4];
#pragma unroll
            for (int mi = 0; mi < 4; mi++)
                ldsm4(af[mi][0], af[mi][1], af[mi][2], af[mi][3],
                      as_u + (uint32_t)(s * A_STAGE + a_off[mi] + ks) * 4);
            uint32_t bf[4][2];
#pragma unroll
            for (int np = 0; np < 2; np++)
                ldsm4(bf[2 * np][0], bf[2 * np][1], bf[2 * np + 1][0], bf[2 * np + 1][1],
                      ks_u + (uint32_t)(s * A_STAGE + b_off[np] + ks) * 4);
#pragma unroll
            for (int mi = 0; mi < 4; mi++)
#pragma unroll
                for (int ni = 0; ni < 4; ni++)
                    mma_tf32(acc[mi][ni], af[mi], bf[ni]);
        }
        __syncthreads();
    }

    const float scale = rsqrtf((float)D);
#pragma unroll
    for (int mi = 0; mi < 4; mi++) {
        int gi0 = m0 + wm + mi * 16 + g;
#pragma unroll
        for (int ni = 0; ni < 4; ni++) {
            int gj = n0 + wn + ni * 8 + 2 * tg;
            float2 v0 = {acc[mi][ni][0] * scale, acc[mi][ni][1] * scale};
            float2 v1 = {acc[mi][ni][2] * scale, acc[mi][ni][3] * scale};
            *(float2*)(P + (size_t)gi0 * S + gj) = v0;
            *(float2*)(P + (size_t)(gi0 + 8) * S + gj) = v1;
        }
    }
}

// ---------------------------------------------------------------------------
// Kernel 3: softmax (2 passes). Stores tf32-rounded UNNORMALIZED exp + row sum;
// pv epilogue divides. grid=(S,B)
// ---------------------------------------------------------------------------
__global__ __launch_bounds__(256) void softmax_kernel()
{
    const int i = blockIdx.x;
    const int b = blockIdx.y;
    float* row = g_P + ((size_t)b * S + i) * S;
    const int tid = threadIdx.x;
    const int Jend = ((i >> 7) + 1) << 7;

    __shared__ float red[256];

    float m = -INFINITY;
    for (int j = tid; j <= i; j += 256) m = fmaxf(m, row[j]);
    red[tid] = m;
    __syncthreads();
    for (int s = 128; s > 0; s >>= 1) {
        if (tid < s) red[tid] = fmaxf(red[tid], red[tid + s]);
        __syncthreads();
    }
    const float mx = red[0];
    __syncthreads();

    float sum = 0.f;
    for (int j = tid; j < Jend; j += 256) {
        if (j <= i) {
            float e = __uint_as_float(f2tf32(__expf(row[j] - mx)));
            row[j] = e;
            sum += e;
        } else {
            row[j] = 0.f;
        }
    }
    red[tid] = sum;
    __syncthreads();
    for (int s = 128; s > 0; s >>= 1) {
        if (tid < s) red[tid] += red[tid + s];
        __syncthreads();
    }
    if (tid == 0) g_sum[b * S + i] = red[0];
}

// ---------------------------------------------------------------------------
// Kernel 4: O = P @ V, causal truncation, normalize in epilogue. grid=(4,16,B)
// ---------------------------------------------------------------------------
__global__ __launch_bounds__(256, 2) void pv_tc(float* __restrict__ outp)
{
    const int nt = blockIdx.x;
    const int mt = blockIdx.y;
    const int b = blockIdx.z;

    extern __shared__ float smem[];
    float* BsF = smem + 2 * A_STAGE;
    const uint32_t as_u = (uint32_t)__cvta_generic_to_shared(smem);

    const float* P = g_P + (size_t)b * S * S;
    const float* V = g_V + (size_t)b * S * D;
    float* O = outp + (size_t)b * S * D;

    const int m0 = mt * 128;
    const int n0 = nt * 128;
    const int tid = threadIdx.x;
    const int warp = tid >> 5, lane = tid & 31;
    const int g = lane >> 2, tg = lane & 3;
    const int sub = lane >> 3, li = lane & 7;
    const int wm = (warp >> 2) * 64, wn = (warp & 3) * 32;
    const int kmax = (mt + 1) * 128;

    const int ar = tid >> 3, ac = (tid & 7) * 4;
    const int br = tid >> 5, bc = (tid & 31) * 4;

    int a_off[4];
#pragma unroll
    for (int mi = 0; mi < 4; mi++)
        a_off[mi] = (wm + mi * 16 + (sub & 1) * 8 + li) * APAD + (sub >> 1) * 4;

    float acc[4][4][4];
#pragma unroll
    for (int mi = 0; mi < 4; mi++)
#pragma unroll
        for (int ni = 0; ni < 4; ni++)
#pragma unroll
            for (int r = 0; r < 4; r++) acc[mi][ni][r] = 0.f;

    auto load_stage = [&](int st, int k0) {
#pragma unroll
        for (int it = 0; it < 4; it++) {
            int row = ar + it * 32;
            cpa16(as_u + (uint32_t)(st * A_STAGE + row * APAD + ac) * 4,
                  P + (size_t)(m0 + row) * S + k0 + ac);
        }
        uint32_t bs_u = as_u + 2u * A_STAGE * 4;
#pragma unroll
        for (int it = 0; it < 4; it++) {
            int row = br + it * 8;
            cpa16(bs_u + (uint32_t)(st * B_STAGE + row * BPAD + bc) * 4,
                  V + (size_t)(k0 + row) * D + n0 + bc);
        }
        cpa_commit();
    };

    load_stage(0, 0);
    int s = 0;
    for (int k0 = 0; k0 < kmax; k0 += 32, s ^= 1) {
        const bool has_next = (k0 + 32 < kmax);
        if (has_next) { load_stage(s ^ 1, k0 + 32); cpa_wait1(); }
        else          { cpa_wait0(); }
        __syncthreads();

#pragma unroll
        for (int ks = 0; ks < 32; ks += 8) {
            uint32_t af[4][4];
#pragma unroll
            for (int mi = 0; mi < 4; mi++)
                ldsm4(af[mi][0], af[mi][1], af[mi][2], af[mi][3],
                      as_u + (uint32_t)(s * A_STAGE + a_off[mi] + ks) * 4);
            uint32_t bf[4][2];
#pragma unroll
            for (int ni = 0; ni < 4; ni++) {
                const float* bp = BsF + s * B_STAGE + (ks + tg) * BPAD + wn + ni * 8 + g;
                bf[ni][0] = __float_as_uint(bp[0]);
                bf[ni][1] = __float_as_uint(bp[4 * BPAD]);
            }
#pragma unroll
            for (int mi = 0; mi < 4; mi++)
#pragma unroll
                for (int ni = 0; ni < 4; ni++)
                    mma_tf32(acc[mi][ni], af[mi], bf[ni]);
        }
        __syncthreads();
    }

#pragma unroll
    for (int mi = 0; mi < 4; mi++) {
        int row0 = m0 + wm + mi * 16 + g;
        float inv0 = 1.f / g_sum[b * S + row0];
        float inv1 = 1.f / g_sum[b * S + row0 + 8];
#pragma unroll
        for (int ni = 0; ni < 4; ni++) {
            int col = n0 + wn + ni * 8 + 2 * tg;
            float2 v0 = {acc[mi][ni][0] * inv0, acc[mi][ni][1] * inv0};
            float2 v1 = {acc[mi][ni][2] * inv1, acc[mi][ni][3] * inv1};
            *(float2*)(O + (size_t)row0 * D + col) = v0;
            *(float2*)(O + (size_t)(row0 + 8) * D + col) = v1;
        }
    }
}

// ---------------------------------------------------------------------------
extern "C" void kernel_launch(void* const* d_in, const int* in_sizes, int n_in,
                              void* d_out, int out_size)
{
    const float* x  = (const float*)d_in[0];
    const float* wq = (const float*)d_in[1];
    const float* bq = (const float*)d_in[2];
    const float* wk = (const float*)d_in[3];
    const float* bk = (const float*)d_in[4];
    const float* wv = (const float*)d_in[5];
    const float* bv = (const float*)d_in[6];
    float* out = (float*)d_out;

    const int smem_ab = (2 * A_STAGE + 2 * B_STAGE) * 4;  // 71680 B
    const int smem_aa = (4 * A_STAGE) * 4;                // 73728 B
    cudaFuncSetAttribute(qkv_tc,   cudaFuncAttributeMaxDynamicSharedMemorySize, smem_ab);
    cudaFuncSetAttribute(scores_tc, cudaFuncAttributeMaxDynamicSharedMemorySize, smem_aa);
    cudaFuncSetAttribute(pv_tc,    cudaFuncAttributeMaxDynamicSharedMemorySize, smem_ab);

    dim3 blk(256);
    qkv_tc<<<dim3(D / 128, M_TOT / 128, 3), blk, smem_ab>>>(x, wq, bq, wk, bk, wv, bv);
    scores_tc<<<dim3(S / 128, S / 128, B), blk, smem_aa>>>();
    softmax_kernel<<<dim3(S, B), blk>>>();
    pv_tc<<<dim3(D / 128, S / 128, B), blk, smem_ab>>>(out);
}